// round 14
// baseline (speedup 1.0000x reference)
#include <cuda_runtime.h>
#include <cuda_fp16.h>
#include <cstdint>
#include <cstddef>

#define T_STEPS  511
#define BATCH    1024
#define NBLK     128
#define NTHREADS 256
#define XELEM    66977792u     /* 511*1024*128 */
#define XWORDS4  16744448u     /* XELEM/4 */
#define XPROJ_FLOATS 535822336u /* 511*8*16*8192 floats = ~2.0GiB */

// ---- recurrence kernel smem layout (bytes) ----
#define R_BH   0u              /* W_hh hi: 64 x 528B = 33792 */
#define R_BL   33792u          /* W_hh lo                    */
#define R_AH   67584u          /* A(h) hi: 128 x 528B = 67584*/
#define R_AL   135168u         /* A(h) lo                    */
#define R_HSH  202752u         /* h staging hi: 4096 (dedicated, no alias) */
#define R_HSL  206848u         /* h staging lo: 4096         */
#define SMEM_R 210944u

// ---- x_proj prepass smem layout ----
#define P_BH   0u              /* W_ih hi: 64 x 272B = 17408 */
#define P_BL   17408u
#define P_AH   34816u          /* x hi: 128 x 272B = 34816   */
#define P_AL   69632u
#define SMEM_P 104448u

// ---------------------------------------------------------------- helpers
__device__ __forceinline__ uint32_t smem_u32(const void* p) {
    uint32_t a;
    asm("{ .reg .u64 t; cvta.to.shared.u64 t, %1; cvt.u32.u64 %0, t; }"
        : "=r"(a) : "l"(p));
    return a;
}
__device__ __forceinline__ void ldsm4(uint32_t* r, uint32_t addr) {
    asm volatile("ldmatrix.sync.aligned.m8n8.x4.shared.b16 {%0,%1,%2,%3}, [%4];"
        : "=r"(r[0]), "=r"(r[1]), "=r"(r[2]), "=r"(r[3]) : "r"(addr));
}
__device__ __forceinline__ void mma16816(float* c, const uint32_t* a,
                                         const uint32_t* b) {
    asm volatile(
        "mma.sync.aligned.m16n8k16.row.col.f32.f16.f16.f32 "
        "{%0,%1,%2,%3}, {%4,%5,%6,%7}, {%8,%9}, {%0,%1,%2,%3};"
        : "+f"(c[0]), "+f"(c[1]), "+f"(c[2]), "+f"(c[3])
        : "r"(a[0]), "r"(a[1]), "r"(a[2]), "r"(a[3]), "r"(b[0]), "r"(b[1]));
}
__device__ __forceinline__ void cpa16(uint32_t dst, const void* src) {
    asm volatile("cp.async.cg.shared.global [%0], [%1], 16;"
        :: "r"(dst), "l"(src) : "memory");
}
#define CP_COMMIT() asm volatile("cp.async.commit_group;" ::: "memory")
#define CP_WAIT0()  asm volatile("cp.async.wait_group 0;"  ::: "memory")
#define CP_WAIT1()  asm volatile("cp.async.wait_group 1;"  ::: "memory")

__device__ __forceinline__ float sigf(float x) {
    return __fdividef(1.f, 1.f + __expf(-x));
}
__device__ __forceinline__ float tanhf_fast(float x) {
    return 1.f - __fdividef(2.f, __expf(2.f * x) + 1.f);
}

// ---------------------------------------------------------------- scratch
__device__ __align__(16) __half g_xhi[XELEM];
__device__ __align__(16) __half g_xlo[XELEM];
__device__ __align__(16) float  g_xproj[XPROJ_FLOATS];
__device__ __align__(16) __half g_hhi[2][BATCH * 256];
__device__ __align__(16) __half g_hlo[2][BATCH * 256];
__device__ unsigned g_cnt[8];
__device__ unsigned g_gen[8];

// ---------------------------------------------------------------- prepass 1
__global__ void lstm_split_x(const float4* __restrict__ x) {
    uint32_t i = blockIdx.x * blockDim.x + threadIdx.x;
    if (i >= XWORDS4) return;
    float4 v = x[i];
    union U { __half h[4]; uint2 u; } ph, pl;
    ph.h[0] = __float2half_rn(v.x); ph.h[1] = __float2half_rn(v.y);
    ph.h[2] = __float2half_rn(v.z); ph.h[3] = __float2half_rn(v.w);
    pl.h[0] = __float2half_rn(v.x - __half2float(ph.h[0]));
    pl.h[1] = __float2half_rn(v.y - __half2float(ph.h[1]));
    pl.h[2] = __float2half_rn(v.z - __half2float(ph.h[2]));
    pl.h[3] = __float2half_rn(v.w - __half2float(ph.h[3]));
    ((uint2*)g_xhi)[i] = ph.u;
    ((uint2*)g_xlo)[i] = pl.u;
}

// ---------------------------------------------------------------- prepass 2
// x_proj[t, mb, nb] fragment tile = x[t, mb*128:+128, :] @ W_ih(nb cols)^T + bias
// Stored in per-thread fragment order: frag[bx][tid*32 + (mi*4+ni)*4 + e].
__global__ void __launch_bounds__(256, 2) lstm_xproj(
    const float* __restrict__ W_ih,
    const float* __restrict__ b_ih, const float* __restrict__ b_hh)
{
    extern __shared__ char sm[];
    const uint32_t sb = smem_u32(sm);
    const int tid  = threadIdx.x;
    const int lane = tid & 31;
    const int w    = tid >> 5;
    const int wm   = w >> 1, wn = w & 1;
    const int bx   = blockIdx.x;
    const int nb   = bx & 15;
    const int mb   = (bx >> 4) & 7;
    const int t    = bx >> 7;

    // B = W_ih slice, hi/lo, col-interleaved (g=(n>>3)&3, ch=(n&7)+((n>>5)<<3))
    for (int idx = tid; idx < 64 * 128; idx += 256) {
        int n = idx >> 7, k = idx & 127;
        int g = (n >> 3) & 3, ch = (n & 7) + ((n >> 5) << 3);
        int wr = g * 256 + nb * 16 + ch;
        float v = W_ih[wr * 128 + k];
        __half hi = __float2half_rn(v);
        __half lo = __float2half_rn(v - __half2float(hi));
        *(__half*)(sm + P_BH + n * 272 + k * 2) = hi;
        *(__half*)(sm + P_BL + n * 272 + k * 2) = lo;
    }
    // A = x rows (hi/lo) via cp.async.  Row = 128 halves = 256 BYTES ->
    // 16 chunks of 16B per row (BUGFIX vs R12 which only filled 8).
    const __half* xh = g_xhi + ((size_t)t * BATCH + mb * 128) * 128;
    const __half* xl = g_xlo + ((size_t)t * BATCH + mb * 128) * 128;
    for (int idx = tid; idx < 128 * 16; idx += 256) {
        int row = idx >> 4, kc = idx & 15;
        uint32_t d = sb + P_AH + row * 272 + kc * 16;
        cpa16(d, xh + row * 128 + kc * 8);
        cpa16(d + (P_AL - P_AH), xl + row * 128 + kc * 8);
    }
    CP_COMMIT(); CP_WAIT0();
    __syncthreads();

    float Cacc[2][4][4];
#pragma unroll
    for (int mi = 0; mi < 2; mi++)
#pragma unroll
        for (int ni = 0; ni < 4; ni++)
#pragma unroll
            for (int e = 0; e < 4; e++) Cacc[mi][ni][e] = 0.f;

#pragma unroll
    for (int ks = 0; ks < 8; ks++) {
        uint32_t ah[2][4], al[2][4], bh2[2][4], bl2[2][4];
#pragma unroll
        for (int mi = 0; mi < 2; mi++) {
            uint32_t row = wm * 32 + mi * 16 + (lane & 15);
            uint32_t a = sb + P_AH + row * 272 + ks * 32 + ((lane >> 4) << 4);
            ldsm4(ah[mi], a);
            ldsm4(al[mi], a + (P_AL - P_AH));
        }
#pragma unroll
        for (int gn = 0; gn < 2; gn++) {
            uint32_t n = wn * 32 + gn * 16 + (lane & 7) + ((lane >> 4) << 3);
            uint32_t ko = ((lane >> 3) & 1) * 16;
            uint32_t a = sb + P_BH + n * 272 + ks * 32 + ko;
            ldsm4(bh2[gn], a);
            ldsm4(bl2[gn], a + (P_BL - P_BH));
        }
#pragma unroll
        for (int mi = 0; mi < 2; mi++)
#pragma unroll
            for (int ni = 0; ni < 4; ni++) {
                const uint32_t* bH = &bh2[ni >> 1][(ni & 1) * 2];
                const uint32_t* bL = &bl2[ni >> 1][(ni & 1) * 2];
                mma16816(Cacc[mi][ni], ah[mi], bH);
                mma16816(Cacc[mi][ni], al[mi], bH);
                mma16816(Cacc[mi][ni], ah[mi], bL);
            }
    }

    // add bias, store fragments
    const int lc2 = 2 * (lane & 3);
#pragma unroll
    for (int ni = 0; ni < 4; ni++)
#pragma unroll
        for (int cc = 0; cc < 2; cc++) {
            int col = wn * 32 + ni * 8 + lc2 + cc;
            int g = (col >> 3) & 3, ch = (col & 7) + ((col >> 5) << 3);
            int wr = g * 256 + nb * 16 + ch;
            float b = b_ih[wr] + b_hh[wr];
#pragma unroll
            for (int mi = 0; mi < 2; mi++) {
                Cacc[mi][ni][cc] += b;
                Cacc[mi][ni][2 + cc] += b;
            }
        }
    const float* cf = &Cacc[0][0][0];
    float4* dst = (float4*)g_xproj + (size_t)bx * 2048 + tid * 8;
#pragma unroll
    for (int q = 0; q < 8; q++)
        dst[q] = make_float4(cf[q * 4], cf[q * 4 + 1], cf[q * 4 + 2], cf[q * 4 + 3]);
}

// ---------------------------------------------------------------- barrier
__device__ __forceinline__ void group_barrier(int mb) {
    __syncthreads();
    if (threadIdx.x == 0) {
        __threadfence();
        unsigned g0 = ((volatile unsigned*)g_gen)[mb];
        if (atomicAdd(&g_cnt[mb], 1u) == 15u) {
            ((volatile unsigned*)g_cnt)[mb] = 0u;
            __threadfence();
            atomicAdd(&g_gen[mb], 1u);
        } else {
            while (((volatile unsigned*)g_gen)[mb] == g0) { __nanosleep(32); }
        }
        __threadfence();
    }
    __syncthreads();
}

// ---------------------------------------------------------------- main
__global__ void __launch_bounds__(NTHREADS, 1) lstm_persistent(
    const float* __restrict__ W_hh,
    const float* __restrict__ hx0, const float* __restrict__ cx0,
    float* __restrict__ out)
{
    extern __shared__ char sm[];
    const uint32_t sb = smem_u32(sm);

    const int tid  = threadIdx.x;
    const int lane = tid & 31;
    const int w    = tid >> 5;
    const int wm   = w >> 1;          // 0..3: rows [wm*32, +32)
    const int wn   = w & 1;           // 0..1: cols [wn*32, +32)
    const int mb   = blockIdx.x >> 4; // batch block (128 rows)
    const int nb   = blockIdx.x & 15; // 16 h-channels

    // ---- build B = W_hh slice (hi/lo fp16, [n][k] K-contig, stride 528B) ----
    for (int idx = tid; idx < 64 * 256; idx += NTHREADS) {
        int n = idx >> 8, k = idx & 255;
        int g = (n >> 3) & 3, ch = (n & 7) + ((n >> 5) << 3);
        int wr = g * 256 + nb * 16 + ch;
        float v = W_hh[wr * 256 + k];
        __half hi = __float2half_rn(v);
        __half lo = __float2half_rn(v - __half2float(hi));
        *(__half*)(sm + R_BH + n * 528 + k * 2) = hi;
        *(__half*)(sm + R_BL + n * 528 + k * 2) = lo;
    }

    // ---- init c registers + h0 ping buffer 0 ----
    const int lc2 = 2 * (lane & 3);
    float c_reg[8], h_f[8];
#pragma unroll
    for (int mi = 0; mi < 2; mi++)
#pragma unroll
        for (int rr = 0; rr < 2; rr++)
#pragma unroll
            for (int cc = 0; cc < 2; cc++) {
                int ch = 8 * wn + lc2 + cc;
                c_reg[mi * 4 + rr * 2 + cc] = cx0[nb * 16 + ch];
                h_f[mi * 4 + rr * 2 + cc] = 0.f;
            }
    if (tid < 128) {
        int r = tid;
        size_t o = ((size_t)(mb * 128 + r)) * 256 + nb * 16;
#pragma unroll
        for (int ch = 0; ch < 16; ch++) {
            float v = hx0[nb * 16 + ch];
            __half hi = __float2half_rn(v);
            __half lo = __float2half_rn(v - __half2float(hi));
            g_hhi[0][o + ch] = hi;
            g_hlo[0][o + ch] = lo;
        }
    }
    group_barrier(mb);

    const size_t fragstride = 2048;  // float4 per (t,mb,nb) block
    // ---- recurrence ----
    for (int t = 0; t < T_STEPS; t++) {
        const int pr = t & 1, pw = pr ^ 1;
        const __half* hh = g_hhi[pr] + (size_t)(mb * 128) * 256;
        const __half* hl = g_hlo[pr] + (size_t)(mb * 128) * 256;

        // init Cacc from precomputed x_proj fragments (bias already folded)
        float Cacc[2][4][4];
        {
            const float4* xp = (const float4*)g_xproj
                + ((size_t)((((t << 3) | mb) << 4) | nb)) * fragstride + tid * 8;
            float* cf = &Cacc[0][0][0];
#pragma unroll
            for (int q = 0; q < 8; q++) {
                float4 v = xp[q];
                cf[q * 4 + 0] = v.x; cf[q * 4 + 1] = v.y;
                cf[q * 4 + 2] = v.z; cf[q * 4 + 3] = v.w;
            }
        }

        // issue both K-halves of A(h) as two cp.async groups
#pragma unroll
        for (int half = 0; half < 2; half++) {
            for (int idx = tid; idx < 128 * 16; idx += NTHREADS) {
                int row = idx >> 4, kc = idx & 15;
                uint32_t d = sb + R_AH + row * 528 + half * 256 + kc * 16;
                cpa16(d, hh + row * 256 + half * 128 + kc * 8);
                cpa16(d + (R_AL - R_AH), hl + row * 256 + half * 128 + kc * 8);
            }
            CP_COMMIT();
        }
        CP_WAIT1();          // half 0 landed
        __syncthreads();

#pragma unroll
        for (int half = 0; half < 2; half++) {
            const int hb = half * 256;
#pragma unroll
            for (int ks = 0; ks < 8; ks++) {
                uint32_t ah[2][4], al[2][4], bh2[2][4], bl2[2][4];
#pragma unroll
                for (int mi = 0; mi < 2; mi++) {
                    uint32_t row = wm * 32 + mi * 16 + (lane & 15);
                    uint32_t a = sb + R_AH + row * 528 + hb + ks * 32
                               + ((lane >> 4) << 4);
                    ldsm4(ah[mi], a);
                    ldsm4(al[mi], a + (R_AL - R_AH));
                }
#pragma unroll
                for (int gn = 0; gn < 2; gn++) {
                    uint32_t n = wn * 32 + gn * 16 + (lane & 7)
                               + ((lane >> 4) << 3);
                    uint32_t ko = ((lane >> 3) & 1) * 16;
                    uint32_t a = sb + R_BH + n * 528 + hb + ks * 32 + ko;
                    ldsm4(bh2[gn], a);
                    ldsm4(bl2[gn], a + (R_BL - R_BH));
                }
#pragma unroll
                for (int mi = 0; mi < 2; mi++)
#pragma unroll
                    for (int ni = 0; ni < 4; ni++) {
                        const uint32_t* bH = &bh2[ni >> 1][(ni & 1) * 2];
                        const uint32_t* bL = &bl2[ni >> 1][(ni & 1) * 2];
                        mma16816(Cacc[mi][ni], ah[mi], bH);  // Ahi*Bhi
                        mma16816(Cacc[mi][ni], al[mi], bH);  // Alo*Bhi
                        mma16816(Cacc[mi][ni], ah[mi], bL);  // Ahi*Blo
                    }
            }
            if (half == 0) { CP_WAIT0(); __syncthreads(); }
        }

        // ---- in-register epilogue: gates -> (h,c); h hi/lo to staging ----
        // (staging region is DEDICATED smem -> no conflict with A reads)
#pragma unroll
        for (int mi = 0; mi < 2; mi++)
#pragma unroll
            for (int rr = 0; rr < 2; rr++)
#pragma unroll
                for (int cc = 0; cc < 2; cc++) {
                    int ci = rr * 2 + cc;
                    int idx = mi * 4 + ci;
                    int ch = 8 * wn + lc2 + cc;
                    float i_ = sigf(Cacc[mi][0][ci]);
                    float f_ = sigf(Cacc[mi][1][ci]);
                    float g_ = tanhf_fast(Cacc[mi][2][ci]);
                    float o_ = sigf(Cacc[mi][3][ci]);
                    float cn = f_ * c_reg[idx] + i_ * g_;
                    c_reg[idx] = cn;
                    float hN = o_ * tanhf_fast(cn);
                    h_f[idx] = hN;
                    int r = wm * 32 + mi * 16 + (lane >> 2) + rr * 8;
                    __half hi = __float2half_rn(hN);
                    __half lo = __float2half_rn(hN - __half2float(hi));
                    *(__half*)(sm + R_HSH + r * 32 + ch * 2) = hi;
                    *(__half*)(sm + R_HSL + r * 32 + ch * 2) = lo;
                }
        __syncthreads();

        // coalesced h -> gmem ping buffer (256 threads, 16B each)
        {
            int r = tid >> 1, part = tid & 1;
            const uint4* s0 = (const uint4*)(sm + R_HSH + r * 32 + part * 16);
            const uint4* s1 = (const uint4*)(sm + R_HSL + r * 32 + part * 16);
            size_t o = ((size_t)(mb * 128 + r)) * 256 + nb * 16 + part * 8;
            *(uint4*)(g_hhi[pw] + o) = s0[0];
            *(uint4*)(g_hlo[pw] + o) = s1[0];
        }
        group_barrier(mb);
    }

    // ---- output: h (1024x256) then c (1024x256), fp32 ----
#pragma unroll
    for (int mi = 0; mi < 2; mi++)
#pragma unroll
        for (int rr = 0; rr < 2; rr++)
#pragma unroll
            for (int cc = 0; cc < 2; cc++) {
                int idx = mi * 4 + rr * 2 + cc;
                int r = wm * 32 + mi * 16 + (lane >> 2) + rr * 8;
                int ch = 8 * wn + lc2 + cc;
                size_t o = ((size_t)(mb * 128 + r)) * 256 + nb * 16 + ch;
                out[o] = h_f[idx];
                out[(size_t)BATCH * 256 + o] = c_reg[idx];
            }
}

// ---------------------------------------------------------------- launch
extern "C" void kernel_launch(void* const* d_in, const int* in_sizes, int n_in,
                              void* d_out, int out_size) {
    (void)in_sizes; (void)n_in; (void)out_size;
    const float* x    = (const float*)d_in[0];
    const float* W_ih = (const float*)d_in[1];
    const float* W_hh = (const float*)d_in[2];
    const float* b_ih = (const float*)d_in[3];
    const float* b_hh = (const float*)d_in[4];
    const float* hx0  = (const float*)d_in[5];
    const float* cx0  = (const float*)d_in[6];
    float* out = (float*)d_out;

    cudaFuncSetAttribute(lstm_xproj,
                         cudaFuncAttributeMaxDynamicSharedMemorySize, SMEM_P);
    cudaFuncSetAttribute(lstm_persistent,
                         cudaFuncAttributeMaxDynamicSharedMemorySize, SMEM_R);

    lstm_split_x<<<(XWORDS4 + 255) / 256, 256>>>((const float4*)x);
    lstm_xproj<<<T_STEPS * 8 * 16, 256, SMEM_P>>>(W_ih, b_ih, b_hh);
    lstm_persistent<<<NBLK, NTHREADS, SMEM_R>>>(W_hh, hx0, cx0, out);
}

// round 17
// speedup vs baseline: 1.1896x; 1.1896x over previous
#include <cuda_runtime.h>
#include <cuda_fp16.h>
#include <cstdint>
#include <cstddef>

#define T_STEPS  511
#define BATCH    1024
#define NBLK     128
#define NTHREADS 256
#define XELEM    66977792u     /* 511*1024*128 */
#define XWORDS4  16744448u     /* XELEM/4 */

// ---- smem layout (bytes) ----
// B (W cat, K=384): 64 rows x 784B, hi + lo
#define R_BH    0u
#define R_BL    50176u
// A chunk buffers: 2 bufs x (hi 128x208 + lo 128x208)
#define R_ABUF  100352u        /* buf b: hi @ +b*53248, lo @ +b*53248+26624 */
#define R_HSH   206848u        /* h staging hi (dedicated) */
#define R_HSL   210944u        /* h staging lo             */
#define R_BIAS  215040u        /* 64 floats                */
#define SMEM_R  215296u

// ---------------------------------------------------------------- helpers
__device__ __forceinline__ uint32_t smem_u32(const void* p) {
    uint32_t a;
    asm("{ .reg .u64 t; cvta.to.shared.u64 t, %1; cvt.u32.u64 %0, t; }"
        : "=r"(a) : "l"(p));
    return a;
}
__device__ __forceinline__ void ldsm4(uint32_t* r, uint32_t addr) {
    asm volatile("ldmatrix.sync.aligned.m8n8.x4.shared.b16 {%0,%1,%2,%3}, [%4];"
        : "=r"(r[0]), "=r"(r[1]), "=r"(r[2]), "=r"(r[3]) : "r"(addr));
}
__device__ __forceinline__ void mma16816(float* c, const uint32_t* a,
                                         const uint32_t* b) {
    asm volatile(
        "mma.sync.aligned.m16n8k16.row.col.f32.f16.f16.f32 "
        "{%0,%1,%2,%3}, {%4,%5,%6,%7}, {%8,%9}, {%0,%1,%2,%3};"
        : "+f"(c[0]), "+f"(c[1]), "+f"(c[2]), "+f"(c[3])
        : "r"(a[0]), "r"(a[1]), "r"(a[2]), "r"(a[3]), "r"(b[0]), "r"(b[1]));
}
__device__ __forceinline__ void cpa16(uint32_t dst, const void* src) {
    asm volatile("cp.async.cg.shared.global [%0], [%1], 16;"
        :: "r"(dst), "l"(src) : "memory");
}
#define CP_COMMIT() asm volatile("cp.async.commit_group;" ::: "memory")
#define CP_WAIT0()  asm volatile("cp.async.wait_group 0;"  ::: "memory")
#define CP_WAIT1()  asm volatile("cp.async.wait_group 1;"  ::: "memory")

__device__ __forceinline__ float sigf(float x) {
    return __fdividef(1.f, 1.f + __expf(-x));
}
__device__ __forceinline__ float tanhf_fast(float x) {
    return 1.f - __fdividef(2.f, __expf(2.f * x) + 1.f);
}

// ---------------------------------------------------------------- scratch
__device__ __align__(16) __half g_xhi[XELEM];
__device__ __align__(16) __half g_xlo[XELEM];
__device__ __align__(16) __half g_hhi[2][BATCH * 256];
__device__ __align__(16) __half g_hlo[2][BATCH * 256];
__device__ unsigned g_cnt[8 * 32];   /* 128B-spaced slots */
__device__ unsigned g_gen[8 * 32];

// ---------------------------------------------------------------- prepass
__global__ void lstm_split_x(const float4* __restrict__ x) {
    uint32_t i = blockIdx.x * blockDim.x + threadIdx.x;
    if (i >= XWORDS4) return;
    float4 v = x[i];
    union U { __half h[4]; uint2 u; } ph, pl;
    ph.h[0] = __float2half_rn(v.x); ph.h[1] = __float2half_rn(v.y);
    ph.h[2] = __float2half_rn(v.z); ph.h[3] = __float2half_rn(v.w);
    pl.h[0] = __float2half_rn(v.x - __half2float(ph.h[0]));
    pl.h[1] = __float2half_rn(v.y - __half2float(ph.h[1]));
    pl.h[2] = __float2half_rn(v.z - __half2float(ph.h[2]));
    pl.h[3] = __float2half_rn(v.w - __half2float(ph.h[3]));
    ((uint2*)g_xhi)[i] = ph.u;
    ((uint2*)g_xlo)[i] = pl.u;
}

// ---------------------------------------------------------------- barrier
// Only the 16 CTAs sharing a batch-block depend on each other.
__device__ __forceinline__ void group_barrier(int mb) {
    __syncthreads();
    if (threadIdx.x == 0) {
        __threadfence();
        unsigned g0 = ((volatile unsigned*)g_gen)[mb * 32];
        if (atomicAdd(&g_cnt[mb * 32], 1u) == 15u) {
            ((volatile unsigned*)g_cnt)[mb * 32] = 0u;
            __threadfence();
            atomicAdd(&g_gen[mb * 32], 1u);
        } else {
            while (((volatile unsigned*)g_gen)[mb * 32] == g0) {}
        }
        __threadfence();
    }
    __syncthreads();
}

// ---------------------------------------------------------------- fill/compute
// A chunk c covers K halves [c*96, c*96+96): 12 pieces of 8 halves per row.
__device__ __forceinline__ void fill_chunk(uint32_t sb, int c, int buf,
    const __half* __restrict__ xh, const __half* __restrict__ xl,
    const __half* __restrict__ hh, const __half* __restrict__ hl, int tid)
{
    uint32_t ah = sb + R_ABUF + (uint32_t)buf * 53248u;
    for (int idx = tid; idx < 128 * 12; idx += NTHREADS) {
        int row = idx / 12, p = idx - row * 12;
        int gk = c * 96 + p * 8;
        const __half *sh, *sl;
        if (gk < 128) { sh = xh + row * 128 + gk;
                        sl = xl + row * 128 + gk; }
        else          { sh = hh + row * 256 + (gk - 128);
                        sl = hl + row * 256 + (gk - 128); }
        uint32_t d = ah + row * 208 + p * 16;
        cpa16(d, sh);
        cpa16(d + 26624u, sl);
    }
    CP_COMMIT();
}

__device__ __forceinline__ void compute_chunk(uint32_t sb, int c, int buf,
    int wm, int wn, int lane, float Cacc[2][4][4])
{
    uint32_t ah = sb + R_ABUF + (uint32_t)buf * 53248u;
    const uint32_t kb = (uint32_t)c * 192u;   // B k-byte offset
#pragma unroll
    for (int ks = 0; ks < 6; ks++) {
        uint32_t ahf[2][4], alf[2][4], bh2[2][4], bl2[2][4];
#pragma unroll
        for (int mi = 0; mi < 2; mi++) {
            uint32_t row = wm * 32 + mi * 16 + (lane & 15);
            uint32_t a = ah + row * 208 + ks * 32 + ((lane >> 4) << 4);
            ldsm4(ahf[mi], a);
            ldsm4(alf[mi], a + 26624u);
        }
#pragma unroll
        for (int gn = 0; gn < 2; gn++) {
            uint32_t n = wn * 32 + gn * 16 + (lane & 7) + ((lane >> 4) << 3);
            uint32_t ko = ((lane >> 3) & 1) * 16;
            uint32_t a = sb + R_BH + n * 784 + kb + ks * 32 + ko;
            ldsm4(bh2[gn], a);
            ldsm4(bl2[gn], a + (R_BL - R_BH));
        }
#pragma unroll
        for (int mi = 0; mi < 2; mi++)
#pragma unroll
            for (int ni = 0; ni < 4; ni++) {
                const uint32_t* bH = &bh2[ni >> 1][(ni & 1) * 2];
                const uint32_t* bL = &bl2[ni >> 1][(ni & 1) * 2];
                mma16816(Cacc[mi][ni], ahf[mi], bH);  // Ahi*Bhi
                mma16816(Cacc[mi][ni], alf[mi], bH);  // Alo*Bhi
                mma16816(Cacc[mi][ni], ahf[mi], bL);  // Ahi*Blo
            }
    }
}

// ---------------------------------------------------------------- main
__global__ void __launch_bounds__(NTHREADS, 1) lstm_persistent(
    const float* __restrict__ W_ih, const float* __restrict__ W_hh,
    const float* __restrict__ b_ih, const float* __restrict__ b_hh,
    const float* __restrict__ hx0, const float* __restrict__ cx0,
    float* __restrict__ out)
{
    extern __shared__ char sm[];
    const uint32_t sb = smem_u32(sm);

    const int tid  = threadIdx.x;
    const int lane = tid & 31;
    const int w    = tid >> 5;
    const int wm   = w >> 1;          // 0..3: rows [wm*32, +32)
    const int wn   = w & 1;           // 0..1: cols [wn*32, +32)
    const int mb   = blockIdx.x >> 4; // batch block (128 rows)
    const int nb   = blockIdx.x & 15; // 16 h-channels

    // ---- build B tiles (64 rows x 384 cols bf16, hi/lo, stride 784B) ----
    for (int idx = tid; idx < 64 * 384; idx += NTHREADS) {
        int n = idx / 384, k = idx - n * 384;
        int g = (n >> 3) & 3, ch = (n & 7) + ((n >> 5) << 3);
        int wr = g * 256 + nb * 16 + ch;
        float v = (k < 128) ? W_ih[wr * 128 + k] : W_hh[wr * 256 + (k - 128)];
        __half hi = __float2half_rn(v);
        __half lo = __float2half_rn(v - __half2float(hi));
        *(__half*)(sm + R_BH + n * 784 + k * 2) = hi;
        *(__half*)(sm + R_BL + n * 784 + k * 2) = lo;
    }
    if (tid < 64) {
        int g = (tid >> 3) & 3, ch = (tid & 7) + ((tid >> 5) << 3);
        int wr = g * 256 + nb * 16 + ch;
        ((float*)(sm + R_BIAS))[tid] = b_ih[wr] + b_hh[wr];
    }

    // ---- init c registers + h0 ping buffer 0 ----
    const int lc2 = 2 * (lane & 3);
    float c_reg[8], h_f[8];
#pragma unroll
    for (int mi = 0; mi < 2; mi++)
#pragma unroll
        for (int rr = 0; rr < 2; rr++)
#pragma unroll
            for (int cc = 0; cc < 2; cc++) {
                int ch = 8 * wn + lc2 + cc;
                c_reg[mi * 4 + rr * 2 + cc] = cx0[nb * 16 + ch];
                h_f[mi * 4 + rr * 2 + cc] = 0.f;
            }
    if (tid < 128) {
        int r = tid;
        size_t o = ((size_t)(mb * 128 + r)) * 256 + nb * 16;
#pragma unroll
        for (int ch = 0; ch < 16; ch++) {
            float v = hx0[nb * 16 + ch];
            __half hi = __float2half_rn(v);
            __half lo = __float2half_rn(v - __half2float(hi));
            g_hhi[0][o + ch] = hi;
            g_hlo[0][o + ch] = lo;
        }
    }

    // prefetch chunk0 (pure x) of t=0 BEFORE the publish barrier
    {
        const __half* xh0 = g_xhi + ((size_t)0 * BATCH + mb * 128) * 128;
        const __half* xl0 = g_xlo + ((size_t)0 * BATCH + mb * 128) * 128;
        fill_chunk(sb, 0, 0, xh0, xl0, nullptr, nullptr, tid);
    }
    group_barrier(mb);

    // ---- recurrence; invariant at loop top: chunk0(t) in flight -> buf0 ----
    for (int t = 0; t < T_STEPS; t++) {
        const int pr = t & 1, pw = pr ^ 1;
        const __half* xh = g_xhi + ((size_t)t * BATCH + mb * 128) * 128;
        const __half* xl = g_xlo + ((size_t)t * BATCH + mb * 128) * 128;
        const __half* hh = g_hhi[pr] + (size_t)(mb * 128) * 256;
        const __half* hl = g_hlo[pr] + (size_t)(mb * 128) * 256;

        float Cacc[2][4][4];
#pragma unroll
        for (int mi = 0; mi < 2; mi++)
#pragma unroll
            for (int ni = 0; ni < 4; ni++)
#pragma unroll
                for (int e = 0; e < 4; e++) Cacc[mi][ni][e] = 0.f;

        fill_chunk(sb, 1, 1, xh, xl, hh, hl, tid);   // pending {f0,f1}
        CP_WAIT1(); __syncthreads();                  // f0 landed
        compute_chunk(sb, 0, 0, wm, wn, lane, Cacc);
        __syncthreads();                              // buf0 free

        fill_chunk(sb, 2, 0, xh, xl, hh, hl, tid);   // pending {f1,f2}
        CP_WAIT1(); __syncthreads();                  // f1 landed
        compute_chunk(sb, 1, 1, wm, wn, lane, Cacc);
        __syncthreads();                              // buf1 free

        fill_chunk(sb, 3, 1, xh, xl, hh, hl, tid);   // pending {f2,f3}
        CP_WAIT1(); __syncthreads();                  // f2 landed
        compute_chunk(sb, 2, 0, wm, wn, lane, Cacc);
        __syncthreads();                              // buf0 free

        {   // prefetch chunk0 of next step (pure x, no h dependency)
            int t2 = (t + 1 < T_STEPS) ? t + 1 : t;
            const __half* xh2 = g_xhi + ((size_t)t2 * BATCH + mb * 128) * 128;
            const __half* xl2 = g_xlo + ((size_t)t2 * BATCH + mb * 128) * 128;
            fill_chunk(sb, 0, 0, xh2, xl2, nullptr, nullptr, tid);
        }
        CP_WAIT1(); __syncthreads();                  // f3 landed
        compute_chunk(sb, 3, 1, wm, wn, lane, Cacc);

        // ---- in-register epilogue: gates -> (h,c); h hi/lo to staging ----
        const float* bias = (const float*)(sm + R_BIAS);
#pragma unroll
        for (int mi = 0; mi < 2; mi++)
#pragma unroll
            for (int rr = 0; rr < 2; rr++)
#pragma unroll
                for (int cc = 0; cc < 2; cc++) {
                    int ci = rr * 2 + cc;
                    int idx = mi * 4 + ci;
                    int ch = 8 * wn + lc2 + cc;
                    float gi = Cacc[mi][0][ci] + bias[wn * 32 + 0  + lc2 + cc];
                    float gf = Cacc[mi][1][ci] + bias[wn * 32 + 8  + lc2 + cc];
                    float gg = Cacc[mi][2][ci] + bias[wn * 32 + 16 + lc2 + cc];
                    float go = Cacc[mi][3][ci] + bias[wn * 32 + 24 + lc2 + cc];
                    float i_ = sigf(gi), f_ = sigf(gf);
                    float g_ = tanhf_fast(gg), o_ = sigf(go);
                    float cn = f_ * c_reg[idx] + i_ * g_;
                    c_reg[idx] = cn;
                    float hN = o_ * tanhf_fast(cn);
                    h_f[idx] = hN;
                    int r = wm * 32 + mi * 16 + (lane >> 2) + rr * 8;
                    __half hi = __float2half_rn(hN);
                    __half lo = __float2half_rn(hN - __half2float(hi));
                    *(__half*)(sm + R_HSH + r * 32 + ch * 2) = hi;
                    *(__half*)(sm + R_HSL + r * 32 + ch * 2) = lo;
                }
        __syncthreads();

        // coalesced h -> gmem ping buffer (256 threads, 16B each)
        {
            int r = tid >> 1, part = tid & 1;
            const uint4* s0 = (const uint4*)(sm + R_HSH + r * 32 + part * 16);
            const uint4* s1 = (const uint4*)(sm + R_HSL + r * 32 + part * 16);
            size_t o = ((size_t)(mb * 128 + r)) * 256 + nb * 16 + part * 8;
            *(uint4*)(g_hhi[pw] + o) = s0[0];
            *(uint4*)(g_hlo[pw] + o) = s1[0];
        }
        group_barrier(mb);
    }
    CP_WAIT0();

    // ---- output: h (1024x256) then c (1024x256), fp32 ----
#pragma unroll
    for (int mi = 0; mi < 2; mi++)
#pragma unroll
        for (int rr = 0; rr < 2; rr++)
#pragma unroll
            for (int cc = 0; cc < 2; cc++) {
                int idx = mi * 4 + rr * 2 + cc;
                int r = wm * 32 + mi * 16 + (lane >> 2) + rr * 8;
                int ch = 8 * wn + lc2 + cc;
                size_t o = ((size_t)(mb * 128 + r)) * 256 + nb * 16 + ch;
                out[o] = h_f[idx];
                out[(size_t)BATCH * 256 + o] = c_reg[idx];
            }
}

// ---------------------------------------------------------------- launch
extern "C" void kernel_launch(void* const* d_in, const int* in_sizes, int n_in,
                              void* d_out, int out_size) {
    (void)in_sizes; (void)n_in; (void)out_size;
    const float* x    = (const float*)d_in[0];
    const float* W_ih = (const float*)d_in[1];
    const float* W_hh = (const float*)d_in[2];
    const float* b_ih = (const float*)d_in[3];
    const float* b_hh = (const float*)d_in[4];
    const float* hx0  = (const float*)d_in[5];
    const float* cx0  = (const float*)d_in[6];
    float* out = (float*)d_out;

    cudaFuncSetAttribute(lstm_persistent,
                         cudaFuncAttributeMaxDynamicSharedMemorySize, SMEM_R);

    lstm_split_x<<<(XWORDS4 + 255) / 256, 256>>>((const float4*)x);
    lstm_persistent<<<NBLK, NTHREADS, SMEM_R>>>(W_ih, W_hh, b_ih, b_hh,
                                                hx0, cx0, out);
}